// round 2
// baseline (speedup 1.0000x reference)
#include <cuda_runtime.h>
#include <cuda_bf16.h>
#include <cstdint>

// ---------------------------------------------------------------------------
// Problem constants (fixed shapes from setup_inputs)
// ---------------------------------------------------------------------------
#define N0 400000
#define N1 100000
#define N2 25000
#define N3 6250
#define DIM 256          // D == H == 256
#define COUT 47

// ---------------------------------------------------------------------------
// Scratch (device globals; allocation-free)
// ---------------------------------------------------------------------------
__device__ float g_agg0[(size_t)N1 * DIM];   // 102.4 MB
__device__ float g_h1  [(size_t)N1 * DIM];   // 102.4 MB
__device__ float g_agg1[(size_t)N2 * DIM];   //  25.6 MB
__device__ float g_h2  [(size_t)N2 * DIM];   //  25.6 MB
__device__ float g_agg2[(size_t)N3 * DIM];   //   6.4 MB

// ---------------------------------------------------------------------------
// Zero fill (float4 grid-stride)
// ---------------------------------------------------------------------------
__global__ void zero_kernel(float4* __restrict__ p, int n4) {
    int i = blockIdx.x * blockDim.x + threadIdx.x;
    int stride = gridDim.x * blockDim.x;
    for (; i < n4; i += stride) p[i] = make_float4(0.f, 0.f, 0.f, 0.f);
}

// ---------------------------------------------------------------------------
// Edge scatter-add: one warp per edge, vectorized red.global.add.v4.f32
// agg[dst[e]] += X[src[e]]  (row width = 256 f32 = 64 float4; 2 per lane)
// ---------------------------------------------------------------------------
__global__ void scatter_add_kernel(const float* __restrict__ X,
                                   const int* __restrict__ src,
                                   const int* __restrict__ dst,
                                   float* __restrict__ agg,
                                   int E) {
    int e = blockIdx.x * 8 + (threadIdx.x >> 5);
    if (e >= E) return;
    int lane = threadIdx.x & 31;
    int s = src[e];
    int d = dst[e];
    const float4* __restrict__ xs = (const float4*)(X + (size_t)s * DIM);
    float* __restrict__ ag = agg + (size_t)d * DIM;
#pragma unroll
    for (int i = 0; i < 2; ++i) {
        int c = lane + i * 32;            // float4 index within row: 0..63
        float4 v = __ldg(&xs[c]);
        asm volatile("red.global.add.v4.f32 [%0], {%1,%2,%3,%4};"
                     :: "l"(ag + c * 4), "f"(v.x), "f"(v.y), "f"(v.z), "f"(v.w)
                     : "memory");
    }
}

// ---------------------------------------------------------------------------
// Fused dual-A GEMM:  C = relu?( A1 @ B1 + A2 @ B2 + bias )
// A: [M, 256] row-major, B: [256, N] row-major, N = 256 (multiple of 128).
// Tiling: 128x128 block tile, BK=16, 256 threads, 8x8 per thread.
// ---------------------------------------------------------------------------
#define BM 128
#define BN 128
#define BK 16
#define TM 8
#define TN 8

__global__ __launch_bounds__(256, 2)
void sage_gemm_kernel(const float* __restrict__ A1, const float* __restrict__ A2,
                      const float* __restrict__ B1, const float* __restrict__ B2,
                      const float* __restrict__ bias, float* __restrict__ C,
                      int M, int relu) {
    __shared__ float As[BK][BM];
    __shared__ float Bs[BK][BN];

    const int tid = threadIdx.x;
    const int tx = tid & 15;          // 0..15
    const int ty = tid >> 4;          // 0..15
    const int m0 = blockIdx.x * BM;
    const int n0 = blockIdx.y * BN;
    const int K = DIM;
    const int N = DIM;

    float acc[TM][TN];
#pragma unroll
    for (int i = 0; i < TM; ++i)
#pragma unroll
        for (int j = 0; j < TN; ++j) acc[i][j] = 0.f;

#pragma unroll 1
    for (int sSel = 0; sSel < 2; ++sSel) {
        const float* __restrict__ A = sSel ? A2 : A1;
        const float* __restrict__ B = sSel ? B2 : B1;
#pragma unroll 1
        for (int kt = 0; kt < K; kt += BK) {
            // Load A tile (BM x BK) -> As transposed. 512 float4, 2 per thread.
#pragma unroll
            for (int i = 0; i < 2; ++i) {
                int id = tid + i * 256;            // 0..511
                int row = id >> 2;                 // BK/4 = 4 float4 per row
                int kc4 = id & 3;
                float4 v;
                int gr = m0 + row;
                if (gr < M) v = *(const float4*)&A[(size_t)gr * K + kt + kc4 * 4];
                else        v = make_float4(0.f, 0.f, 0.f, 0.f);
                As[kc4 * 4 + 0][row] = v.x;
                As[kc4 * 4 + 1][row] = v.y;
                As[kc4 * 4 + 2][row] = v.z;
                As[kc4 * 4 + 3][row] = v.w;
            }
            // Load B tile (BK x BN). 512 float4, 2 per thread.
#pragma unroll
            for (int i = 0; i < 2; ++i) {
                int id = tid + i * 256;
                int krow = id >> 5;                // BN/4 = 32 float4 per row
                int nc4 = id & 31;
                float4 v = *(const float4*)&B[(size_t)(kt + krow) * N + n0 + nc4 * 4];
                *(float4*)&Bs[krow][nc4 * 4] = v;
            }
            __syncthreads();
#pragma unroll
            for (int k = 0; k < BK; ++k) {
                float ar[TM], br[TN];
#pragma unroll
                for (int i = 0; i < TM; ++i) ar[i] = As[k][ty * TM + i];
#pragma unroll
                for (int j = 0; j < TN; ++j) br[j] = Bs[k][tx * TN + j];
#pragma unroll
                for (int i = 0; i < TM; ++i)
#pragma unroll
                    for (int j = 0; j < TN; ++j)
                        acc[i][j] = fmaf(ar[i], br[j], acc[i][j]);
            }
            __syncthreads();
        }
    }

    // Epilogue: bias (+ optional relu), vectorized store
#pragma unroll
    for (int i = 0; i < TM; ++i) {
        int row = m0 + ty * TM + i;
        if (row >= M) continue;
#pragma unroll
        for (int j4 = 0; j4 < TN / 4; ++j4) {
            int col = n0 + tx * TN + j4 * 4;
            float4 v;
            v.x = acc[i][j4 * 4 + 0] + bias[col + 0];
            v.y = acc[i][j4 * 4 + 1] + bias[col + 1];
            v.z = acc[i][j4 * 4 + 2] + bias[col + 2];
            v.w = acc[i][j4 * 4 + 3] + bias[col + 3];
            if (relu) {
                v.x = fmaxf(v.x, 0.f); v.y = fmaxf(v.y, 0.f);
                v.z = fmaxf(v.z, 0.f); v.w = fmaxf(v.w, 0.f);
            }
            *(float4*)&C[(size_t)row * N + col] = v;
        }
    }
}

// ---------------------------------------------------------------------------
// Final layer: out[M, 47] = h @ Wself + agg @ Wneigh + bias  (no relu)
// One block (64 threads) per output row; weights stay hot in L1/L2.
// ---------------------------------------------------------------------------
__global__ __launch_bounds__(64)
void sage_out_kernel(const float* __restrict__ h, const float* __restrict__ agg,
                     const float* __restrict__ Ws, const float* __restrict__ Wn,
                     const float* __restrict__ bias, float* __restrict__ out) {
    int row = blockIdx.x;
    __shared__ float sh[DIM];
    __shared__ float sa[DIM];
    for (int i = threadIdx.x; i < DIM; i += 64) {
        sh[i] = h[(size_t)row * DIM + i];
        sa[i] = agg[(size_t)row * DIM + i];
    }
    __syncthreads();
    int j = threadIdx.x;
    if (j < COUT) {
        float acc = bias[j];
#pragma unroll 4
        for (int k = 0; k < DIM; ++k) {
            acc = fmaf(sh[k], Ws[k * COUT + j], acc);
            acc = fmaf(sa[k], Wn[k * COUT + j], acc);
        }
        out[(size_t)row * COUT + j] = acc;
    }
}

// ---------------------------------------------------------------------------
// Launch
// ---------------------------------------------------------------------------
extern "C" void kernel_launch(void* const* d_in, const int* in_sizes, int n_in,
                              void* d_out, int out_size) {
    const float* x   = (const float*)d_in[0];
    const int* src0  = (const int*)d_in[1];
    const int* dst0  = (const int*)d_in[2];
    const int* src1  = (const int*)d_in[3];
    const int* dst1  = (const int*)d_in[4];
    const int* src2  = (const int*)d_in[5];
    const int* dst2  = (const int*)d_in[6];
    const float* ws0 = (const float*)d_in[7];
    const float* wn0 = (const float*)d_in[8];
    const float* b0  = (const float*)d_in[9];
    const float* ws1 = (const float*)d_in[10];
    const float* wn1 = (const float*)d_in[11];
    const float* b1  = (const float*)d_in[12];
    const float* ws2 = (const float*)d_in[13];
    const float* wn2 = (const float*)d_in[14];
    const float* b2  = (const float*)d_in[15];

    const int E0 = in_sizes[1];
    const int E1 = in_sizes[3];
    const int E2 = in_sizes[5];

    float *agg0, *h1, *agg1, *h2, *agg2;
    cudaGetSymbolAddress((void**)&agg0, g_agg0);
    cudaGetSymbolAddress((void**)&h1,   g_h1);
    cudaGetSymbolAddress((void**)&agg1, g_agg1);
    cudaGetSymbolAddress((void**)&h2,   g_h2);
    cudaGetSymbolAddress((void**)&agg2, g_agg2);

    float* out = (float*)d_out;

    // 1) Zero accumulators
    {
        int n4;
        n4 = N1 * DIM / 4;
        zero_kernel<<<(n4 + 255) / 256 < 8192 ? (n4 + 255) / 256 : 8192, 256>>>((float4*)agg0, n4);
        n4 = N2 * DIM / 4;
        zero_kernel<<<(n4 + 255) / 256, 256>>>((float4*)agg1, n4);
        n4 = N3 * DIM / 4;
        zero_kernel<<<(n4 + 255) / 256, 256>>>((float4*)agg2, n4);
    }

    // 2) Layer 0: scatter + GEMM + relu
    scatter_add_kernel<<<(E0 + 7) / 8, 256>>>(x, src0, dst0, agg0, E0);
    {
        dim3 grid((N1 + BM - 1) / BM, DIM / BN);
        sage_gemm_kernel<<<grid, 256>>>(x, agg0, ws0, wn0, b0, h1, N1, 1);
    }

    // 3) Layer 1
    scatter_add_kernel<<<(E1 + 7) / 8, 256>>>(h1, src1, dst1, agg1, E1);
    {
        dim3 grid((N2 + BM - 1) / BM, DIM / BN);
        sage_gemm_kernel<<<grid, 256>>>(h1, agg1, ws1, wn1, b1, h2, N2, 1);
    }

    // 4) Layer 2 (output, N=47, no relu)
    scatter_add_kernel<<<(E2 + 7) / 8, 256>>>(h2, src2, dst2, agg2, E2);
    sage_out_kernel<<<N3, 64>>>(h2, agg2, ws2, wn2, b2, out);
}

// round 4
// speedup vs baseline: 1.3113x; 1.3113x over previous
#include <cuda_runtime.h>
#include <cuda_bf16.h>
#include <cstdint>

// ---------------------------------------------------------------------------
// Problem constants (fixed shapes from setup_inputs)
// ---------------------------------------------------------------------------
#define N0 400000
#define N1 100000
#define N2 25000
#define N3 6250
#define DIM 256          // D == H == 256
#define COUT 47

// ---------------------------------------------------------------------------
// Scratch (device globals; allocation-free)
// ---------------------------------------------------------------------------
__device__ float g_agg0[(size_t)N1 * DIM];   // 102.4 MB
__device__ float g_h1  [(size_t)N1 * DIM];   // 102.4 MB
__device__ float g_agg1[(size_t)N2 * DIM];   //  25.6 MB
__device__ float g_h2  [(size_t)N2 * DIM];   //  25.6 MB
__device__ float g_agg2[(size_t)N3 * DIM];   //   6.4 MB

// ---------------------------------------------------------------------------
// Zero fill (float4 grid-stride)
// ---------------------------------------------------------------------------
__global__ void zero_kernel(float4* __restrict__ p, int n4) {
    int i = blockIdx.x * blockDim.x + threadIdx.x;
    int stride = gridDim.x * blockDim.x;
    for (; i < n4; i += stride) p[i] = make_float4(0.f, 0.f, 0.f, 0.f);
}

// ---------------------------------------------------------------------------
// Edge scatter-add: one warp per edge. Each lane loads 32B (v8.b32, whole
// 1KB row per warp in one load) with L2::evict_first so the agg accumulator
// keeps L2 residency; then two red.global.add.v4.f32 per lane.
// ---------------------------------------------------------------------------
__global__ void scatter_add_kernel(const float* __restrict__ X,
                                   const int* __restrict__ src,
                                   const int* __restrict__ dst,
                                   float* __restrict__ agg,
                                   int E) {
    int e = blockIdx.x * 8 + (threadIdx.x >> 5);
    if (e >= E) return;
    int lane = threadIdx.x & 31;
    int s = src[e];
    int d = dst[e];
    const float* __restrict__ xs = X + (size_t)s * DIM + lane * 8;
    float* __restrict__ ag = agg + (size_t)d * DIM + lane * 8;
    float v0, v1, v2, v3, v4, v5, v6, v7;
    asm volatile("ld.global.nc.L2::evict_first.v8.b32 "
                 "{%0,%1,%2,%3,%4,%5,%6,%7}, [%8];"
                 : "=f"(v0), "=f"(v1), "=f"(v2), "=f"(v3),
                   "=f"(v4), "=f"(v5), "=f"(v6), "=f"(v7)
                 : "l"(xs));
    asm volatile("red.global.add.v4.f32 [%0], {%1,%2,%3,%4};"
                 :: "l"(ag), "f"(v0), "f"(v1), "f"(v2), "f"(v3) : "memory");
    asm volatile("red.global.add.v4.f32 [%0], {%1,%2,%3,%4};"
                 :: "l"(ag + 4), "f"(v4), "f"(v5), "f"(v6), "f"(v7) : "memory");
}

// ---------------------------------------------------------------------------
// TF32 tensor-core fused dual-A GEMM:
//   C = relu?( A1 @ B1 + A2 @ B2 + bias )
// A: [M, 256] row-major f32, B: [256, 256] row-major f32.
// Block tile 128x128, BK=16, 256 threads = 8 warps in 2(M) x 4(N),
// warp tile 64x32 = 4 mtiles(16) x 4 ntiles(8), mma.sync m16n8k8 tf32.
// ---------------------------------------------------------------------------
#define BM 128
#define BN 128
#define BK 16
#define PAD 8          // 136 % 32 = 8 banks shift per k-row -> conflict-free frags

__device__ __forceinline__ float f2tf32(float x) {
    uint32_t r;
    asm("cvt.rna.tf32.f32 %0, %1;" : "=r"(r) : "f"(x));
    return __uint_as_float(r);
}

__device__ __forceinline__ void mma_tf32(float c[4], const uint32_t a[4], const uint32_t b[2]) {
    asm volatile(
        "mma.sync.aligned.m16n8k8.row.col.f32.tf32.tf32.f32 "
        "{%0,%1,%2,%3}, {%4,%5,%6,%7}, {%8,%9}, {%0,%1,%2,%3};"
        : "+f"(c[0]), "+f"(c[1]), "+f"(c[2]), "+f"(c[3])
        : "r"(a[0]), "r"(a[1]), "r"(a[2]), "r"(a[3]), "r"(b[0]), "r"(b[1]));
}

__global__ __launch_bounds__(256, 2)
void sage_gemm_tc_kernel(const float* __restrict__ A1, const float* __restrict__ A2,
                         const float* __restrict__ B1, const float* __restrict__ B2,
                         const float* __restrict__ bias, float* __restrict__ C,
                         int M, int relu) {
    __shared__ float As[BK][BM + PAD];
    __shared__ float Bs[BK][BN + PAD];

    const int tid  = threadIdx.x;
    const int lane = tid & 31;
    const int wid  = tid >> 5;
    const int tg   = lane & 3;     // thread-in-group (k select)
    const int gid  = lane >> 2;    // group id (row/col select)
    const int wr   = wid >> 2;     // 0..1  -> M
    const int wc   = wid & 3;      // 0..3  -> N
    const int wm   = wr * 64;
    const int wn   = wc * 32;
    const int m0   = blockIdx.x * BM;
    const int n0   = blockIdx.y * BN;
    const int K = DIM, N = DIM;

    float acc[4][4][4];
#pragma unroll
    for (int i = 0; i < 4; ++i)
#pragma unroll
        for (int j = 0; j < 4; ++j)
#pragma unroll
            for (int r = 0; r < 4; ++r) acc[i][j][r] = 0.f;

#pragma unroll 1
    for (int sSel = 0; sSel < 2; ++sSel) {
        const float* __restrict__ A = sSel ? A2 : A1;
        const float* __restrict__ B = sSel ? B2 : B1;
#pragma unroll 1
        for (int kt = 0; kt < K; kt += BK) {
            // --- stage A tile (BM x BK) transposed into As[k][m], tf32-rounded
#pragma unroll
            for (int i = 0; i < 2; ++i) {
                int id = tid + i * 256;            // 0..511
                int row = id >> 2;                 // 0..127
                int kc4 = id & 3;                  // float4 within k-slab
                float4 v;
                int gr = m0 + row;
                if (gr < M) v = *(const float4*)&A[(size_t)gr * K + kt + kc4 * 4];
                else        v = make_float4(0.f, 0.f, 0.f, 0.f);
                As[kc4 * 4 + 0][row] = f2tf32(v.x);
                As[kc4 * 4 + 1][row] = f2tf32(v.y);
                As[kc4 * 4 + 2][row] = f2tf32(v.z);
                As[kc4 * 4 + 3][row] = f2tf32(v.w);
            }
            // --- stage B tile (BK x BN) into Bs[k][n], tf32-rounded
#pragma unroll
            for (int i = 0; i < 2; ++i) {
                int id = tid + i * 256;
                int krow = id >> 5;                // 0..15
                int nc4 = id & 31;
                float4 v = *(const float4*)&B[(size_t)(kt + krow) * N + n0 + nc4 * 4];
                float4 t;
                t.x = f2tf32(v.x); t.y = f2tf32(v.y);
                t.z = f2tf32(v.z); t.w = f2tf32(v.w);
                *(float4*)&Bs[krow][nc4 * 4] = t;
            }
            __syncthreads();

#pragma unroll
            for (int kk = 0; kk < BK; kk += 8) {
                uint32_t af[4][4], bf[4][2];
#pragma unroll
                for (int i = 0; i < 4; ++i) {
                    int mr = wm + i * 16 + gid;
                    af[i][0] = __float_as_uint(As[kk + tg][mr]);
                    af[i][1] = __float_as_uint(As[kk + tg][mr + 8]);
                    af[i][2] = __float_as_uint(As[kk + tg + 4][mr]);
                    af[i][3] = __float_as_uint(As[kk + tg + 4][mr + 8]);
                }
#pragma unroll
                for (int j = 0; j < 4; ++j) {
                    int nc = wn + j * 8 + gid;
                    bf[j][0] = __float_as_uint(Bs[kk + tg][nc]);
                    bf[j][1] = __float_as_uint(Bs[kk + tg + 4][nc]);
                }
#pragma unroll
                for (int i = 0; i < 4; ++i)
#pragma unroll
                    for (int j = 0; j < 4; ++j)
                        mma_tf32(acc[i][j], af[i], bf[j]);
            }
            __syncthreads();
        }
    }

    // --- epilogue: bias (+relu), float2 stores
#pragma unroll
    for (int i = 0; i < 4; ++i) {
#pragma unroll
        for (int rh = 0; rh < 2; ++rh) {           // rh=0 -> c0/c1, rh=1 -> c2/c3
            int row = m0 + wm + i * 16 + gid + rh * 8;
            if (row >= M) continue;
#pragma unroll
            for (int j = 0; j < 4; ++j) {
                int col = n0 + wn + j * 8 + tg * 2;
                float2 v;
                v.x = acc[i][j][rh * 2 + 0] + bias[col + 0];
                v.y = acc[i][j][rh * 2 + 1] + bias[col + 1];
                if (relu) { v.x = fmaxf(v.x, 0.f); v.y = fmaxf(v.y, 0.f); }
                *(float2*)&C[(size_t)row * N + col] = v;
            }
        }
    }
}

// ---------------------------------------------------------------------------
// Final layer: out[M, 47] = h @ Wself + agg @ Wneigh + bias  (no relu)
// ---------------------------------------------------------------------------
__global__ __launch_bounds__(64)
void sage_out_kernel(const float* __restrict__ h, const float* __restrict__ agg,
                     const float* __restrict__ Ws, const float* __restrict__ Wn,
                     const float* __restrict__ bias, float* __restrict__ out) {
    int row = blockIdx.x;
    __shared__ float sh[DIM];
    __shared__ float sa[DIM];
    for (int i = threadIdx.x; i < DIM; i += 64) {
        sh[i] = h[(size_t)row * DIM + i];
        sa[i] = agg[(size_t)row * DIM + i];
    }
    __syncthreads();
    int j = threadIdx.x;
    if (j < COUT) {
        float acc = bias[j];
#pragma unroll 4
        for (int k = 0; k < DIM; ++k) {
            acc = fmaf(sh[k], Ws[k * COUT + j], acc);
            acc = fmaf(sa[k], Wn[k * COUT + j], acc);
        }
        out[(size_t)row * COUT + j] = acc;
    }
}

// ---------------------------------------------------------------------------
// Launch
// ---------------------------------------------------------------------------
extern "C" void kernel_launch(void* const* d_in, const int* in_sizes, int n_in,
                              void* d_out, int out_size) {
    const float* x   = (const float*)d_in[0];
    const int* src0  = (const int*)d_in[1];
    const int* dst0  = (const int*)d_in[2];
    const int* src1  = (const int*)d_in[3];
    const int* dst1  = (const int*)d_in[4];
    const int* src2  = (const int*)d_in[5];
    const int* dst2  = (const int*)d_in[6];
    const float* ws0 = (const float*)d_in[7];
    const float* wn0 = (const float*)d_in[8];
    const float* b0  = (const float*)d_in[9];
    const float* ws1 = (const float*)d_in[10];
    const float* wn1 = (const float*)d_in[11];
    const float* b1  = (const float*)d_in[12];
    const float* ws2 = (const float*)d_in[13];
    const float* wn2 = (const float*)d_in[14];
    const float* b2  = (const float*)d_in[15];

    const int E0 = in_sizes[1];
    const int E1 = in_sizes[3];
    const int E2 = in_sizes[5];

    float *agg0, *h1, *agg1, *h2, *agg2;
    cudaGetSymbolAddress((void**)&agg0, g_agg0);
    cudaGetSymbolAddress((void**)&h1,   g_h1);
    cudaGetSymbolAddress((void**)&agg1, g_agg1);
    cudaGetSymbolAddress((void**)&h2,   g_h2);
    cudaGetSymbolAddress((void**)&agg2, g_agg2);

    float* out = (float*)d_out;

    // 1) Zero accumulators
    {
        int n4;
        n4 = N1 * DIM / 4;
        zero_kernel<<<(n4 + 255) / 256 < 8192 ? (n4 + 255) / 256 : 8192, 256>>>((float4*)agg0, n4);
        n4 = N2 * DIM / 4;
        zero_kernel<<<(n4 + 255) / 256, 256>>>((float4*)agg1, n4);
        n4 = N3 * DIM / 4;
        zero_kernel<<<(n4 + 255) / 256, 256>>>((float4*)agg2, n4);
    }

    // 2) Layer 0: scatter + TC GEMM + relu
    scatter_add_kernel<<<(E0 + 7) / 8, 256>>>(x, src0, dst0, agg0, E0);
    {
        dim3 grid((N1 + BM - 1) / BM, DIM / BN);
        sage_gemm_tc_kernel<<<grid, 256>>>(x, agg0, ws0, wn0, b0, h1, N1, 1);
    }

    // 3) Layer 1
    scatter_add_kernel<<<(E1 + 7) / 8, 256>>>(h1, src1, dst1, agg1, E1);
    {
        dim3 grid((N2 + BM - 1) / BM, DIM / BN);
        sage_gemm_tc_kernel<<<grid, 256>>>(h1, agg1, ws1, wn1, b1, h2, N2, 1);
    }

    // 4) Layer 2 (output, N=47, no relu)
    scatter_add_kernel<<<(E2 + 7) / 8, 256>>>(h2, src2, dst2, agg2, E2);
    sage_out_kernel<<<N3, 64>>>(h2, agg2, ws2, wn2, b2, out);
}

// round 5
// speedup vs baseline: 1.4898x; 1.1361x over previous
#include <cuda_runtime.h>
#include <cuda_bf16.h>
#include <cstdint>

// ---------------------------------------------------------------------------
// Problem constants (fixed shapes from setup_inputs)
// ---------------------------------------------------------------------------
#define N0 400000
#define N1 100000
#define N2 25000
#define N3 6250
#define DIM 256          // D == H == 256
#define COUT 47

// ---------------------------------------------------------------------------
// Scratch (device globals; allocation-free)
// ---------------------------------------------------------------------------
__device__ float g_agg0[(size_t)N1 * DIM];   // 102.4 MB
__device__ float g_h1  [(size_t)N1 * DIM];   // 102.4 MB
__device__ float g_agg1[(size_t)N2 * DIM];   //  25.6 MB
__device__ float g_h2  [(size_t)N2 * DIM];   //  25.6 MB
__device__ float g_agg2[(size_t)N3 * DIM];   //   6.4 MB

// ---------------------------------------------------------------------------
// Zero fill (float4 grid-stride)
// ---------------------------------------------------------------------------
__global__ void zero_kernel(float4* __restrict__ p, int n4) {
    int i = blockIdx.x * blockDim.x + threadIdx.x;
    int stride = gridDim.x * blockDim.x;
    for (; i < n4; i += stride) p[i] = make_float4(0.f, 0.f, 0.f, 0.f);
}

// ---------------------------------------------------------------------------
// Edge scatter-add: one warp per FOUR edges (MLP=8 loads/lane in flight).
// Gather: plain __ldg float4 (x keeps normal L2 residency, reuse ~4).
// Scatter: red.global.add with L2::evict_last policy so the agg accumulator
// (reuse ~16) pins in L2 — and stays hot for the GEMM that reads it next.
// ---------------------------------------------------------------------------
#define EDGES_PER_WARP 4

__global__ void scatter_add_kernel(const float* __restrict__ X,
                                   const int* __restrict__ src,
                                   const int* __restrict__ dst,
                                   float* __restrict__ agg,
                                   int E) {
    uint64_t pol;
    asm("createpolicy.fractional.L2::evict_last.b64 %0, 1.0;" : "=l"(pol));

    int warp = blockIdx.x * (blockDim.x >> 5) + (threadIdx.x >> 5);
    int lane = threadIdx.x & 31;
    int e0 = warp * EDGES_PER_WARP;
    if (e0 >= E) return;

    float4 v[EDGES_PER_WARP][2];
    int   d[EDGES_PER_WARP];
    bool  act[EDGES_PER_WARP];

#pragma unroll
    for (int i = 0; i < EDGES_PER_WARP; ++i) {
        int e = e0 + i;
        act[i] = (e < E);
        if (act[i]) {
            int s = src[e];
            d[i]  = dst[e];
            const float4* __restrict__ xs = (const float4*)(X + (size_t)s * DIM);
            v[i][0] = __ldg(xs + lane);
            v[i][1] = __ldg(xs + lane + 32);
        }
    }
#pragma unroll
    for (int i = 0; i < EDGES_PER_WARP; ++i) {
        if (!act[i]) continue;
        float* __restrict__ ag = agg + (size_t)d[i] * DIM + lane * 4;
        asm volatile("red.global.L2::cache_hint.add.v4.f32 [%0], {%1,%2,%3,%4}, %5;"
                     :: "l"(ag), "f"(v[i][0].x), "f"(v[i][0].y),
                        "f"(v[i][0].z), "f"(v[i][0].w), "l"(pol) : "memory");
        asm volatile("red.global.L2::cache_hint.add.v4.f32 [%0], {%1,%2,%3,%4}, %5;"
                     :: "l"(ag + 128), "f"(v[i][1].x), "f"(v[i][1].y),
                        "f"(v[i][1].z), "f"(v[i][1].w), "l"(pol) : "memory");
    }
}

// ---------------------------------------------------------------------------
// TF32 tensor-core fused dual-A GEMM:
//   C = relu?( A1 @ B1 + A2 @ B2 + bias )
// A: [M, 256] row-major f32, B: [256, 256] row-major f32.
// Block tile 128x128, BK=16, 256 threads = 8 warps in 2(M) x 4(N),
// warp tile 64x32 = 4 mtiles(16) x 4 ntiles(8), mma.sync m16n8k8 tf32.
// ---------------------------------------------------------------------------
#define BM 128
#define BN 128
#define BK 16
#define PAD 8

__device__ __forceinline__ float f2tf32(float x) {
    uint32_t r;
    asm("cvt.rna.tf32.f32 %0, %1;" : "=r"(r) : "f"(x));
    return __uint_as_float(r);
}

__device__ __forceinline__ void mma_tf32(float c[4], const uint32_t a[4], const uint32_t b[2]) {
    asm volatile(
        "mma.sync.aligned.m16n8k8.row.col.f32.tf32.tf32.f32 "
        "{%0,%1,%2,%3}, {%4,%5,%6,%7}, {%8,%9}, {%0,%1,%2,%3};"
        : "+f"(c[0]), "+f"(c[1]), "+f"(c[2]), "+f"(c[3])
        : "r"(a[0]), "r"(a[1]), "r"(a[2]), "r"(a[3]), "r"(b[0]), "r"(b[1]));
}

__global__ __launch_bounds__(256, 2)
void sage_gemm_tc_kernel(const float* __restrict__ A1, const float* __restrict__ A2,
                         const float* __restrict__ B1, const float* __restrict__ B2,
                         const float* __restrict__ bias, float* __restrict__ C,
                         int M, int relu) {
    __shared__ float As[BK][BM + PAD];
    __shared__ float Bs[BK][BN + PAD];

    const int tid  = threadIdx.x;
    const int lane = tid & 31;
    const int wid  = tid >> 5;
    const int tg   = lane & 3;
    const int gid  = lane >> 2;
    const int wr   = wid >> 2;
    const int wc   = wid & 3;
    const int wm   = wr * 64;
    const int wn   = wc * 32;
    const int m0   = blockIdx.x * BM;
    const int n0   = blockIdx.y * BN;
    const int K = DIM, N = DIM;

    float acc[4][4][4];
#pragma unroll
    for (int i = 0; i < 4; ++i)
#pragma unroll
        for (int j = 0; j < 4; ++j)
#pragma unroll
            for (int r = 0; r < 4; ++r) acc[i][j][r] = 0.f;

#pragma unroll 1
    for (int sSel = 0; sSel < 2; ++sSel) {
        const float* __restrict__ A = sSel ? A2 : A1;
        const float* __restrict__ B = sSel ? B2 : B1;
#pragma unroll 1
        for (int kt = 0; kt < K; kt += BK) {
#pragma unroll
            for (int i = 0; i < 2; ++i) {
                int id = tid + i * 256;
                int row = id >> 2;
                int kc4 = id & 3;
                float4 v;
                int gr = m0 + row;
                if (gr < M) v = *(const float4*)&A[(size_t)gr * K + kt + kc4 * 4];
                else        v = make_float4(0.f, 0.f, 0.f, 0.f);
                As[kc4 * 4 + 0][row] = f2tf32(v.x);
                As[kc4 * 4 + 1][row] = f2tf32(v.y);
                As[kc4 * 4 + 2][row] = f2tf32(v.z);
                As[kc4 * 4 + 3][row] = f2tf32(v.w);
            }
#pragma unroll
            for (int i = 0; i < 2; ++i) {
                int id = tid + i * 256;
                int krow = id >> 5;
                int nc4 = id & 31;
                float4 v = *(const float4*)&B[(size_t)(kt + krow) * N + n0 + nc4 * 4];
                float4 t;
                t.x = f2tf32(v.x); t.y = f2tf32(v.y);
                t.z = f2tf32(v.z); t.w = f2tf32(v.w);
                *(float4*)&Bs[krow][nc4 * 4] = t;
            }
            __syncthreads();

#pragma unroll
            for (int kk = 0; kk < BK; kk += 8) {
                uint32_t af[4][4], bf[4][2];
#pragma unroll
                for (int i = 0; i < 4; ++i) {
                    int mr = wm + i * 16 + gid;
                    af[i][0] = __float_as_uint(As[kk + tg][mr]);
                    af[i][1] = __float_as_uint(As[kk + tg][mr + 8]);
                    af[i][2] = __float_as_uint(As[kk + tg + 4][mr]);
                    af[i][3] = __float_as_uint(As[kk + tg + 4][mr + 8]);
                }
#pragma unroll
                for (int j = 0; j < 4; ++j) {
                    int nc = wn + j * 8 + gid;
                    bf[j][0] = __float_as_uint(Bs[kk + tg][nc]);
                    bf[j][1] = __float_as_uint(Bs[kk + tg + 4][nc]);
                }
#pragma unroll
                for (int i = 0; i < 4; ++i)
#pragma unroll
                    for (int j = 0; j < 4; ++j)
                        mma_tf32(acc[i][j], af[i], bf[j]);
            }
            __syncthreads();
        }
    }

#pragma unroll
    for (int i = 0; i < 4; ++i) {
#pragma unroll
        for (int rh = 0; rh < 2; ++rh) {
            int row = m0 + wm + i * 16 + gid + rh * 8;
            if (row >= M) continue;
#pragma unroll
            for (int j = 0; j < 4; ++j) {
                int col = n0 + wn + j * 8 + tg * 2;
                float2 v;
                v.x = acc[i][j][rh * 2 + 0] + bias[col + 0];
                v.y = acc[i][j][rh * 2 + 1] + bias[col + 1];
                if (relu) { v.x = fmaxf(v.x, 0.f); v.y = fmaxf(v.y, 0.f); }
                *(float2*)&C[(size_t)row * N + col] = v;
            }
        }
    }
}

// ---------------------------------------------------------------------------
// Final layer: out[M, 47] = h @ Wself + agg @ Wneigh + bias  (no relu)
// ---------------------------------------------------------------------------
__global__ __launch_bounds__(64)
void sage_out_kernel(const float* __restrict__ h, const float* __restrict__ agg,
                     const float* __restrict__ Ws, const float* __restrict__ Wn,
                     const float* __restrict__ bias, float* __restrict__ out) {
    int row = blockIdx.x;
    __shared__ float sh[DIM];
    __shared__ float sa[DIM];
    for (int i = threadIdx.x; i < DIM; i += 64) {
        sh[i] = h[(size_t)row * DIM + i];
        sa[i] = agg[(size_t)row * DIM + i];
    }
    __syncthreads();
    int j = threadIdx.x;
    if (j < COUT) {
        float acc = bias[j];
#pragma unroll 4
        for (int k = 0; k < DIM; ++k) {
            acc = fmaf(sh[k], Ws[k * COUT + j], acc);
            acc = fmaf(sa[k], Wn[k * COUT + j], acc);
        }
        out[(size_t)row * COUT + j] = acc;
    }
}

// ---------------------------------------------------------------------------
// Launch
// ---------------------------------------------------------------------------
extern "C" void kernel_launch(void* const* d_in, const int* in_sizes, int n_in,
                              void* d_out, int out_size) {
    const float* x   = (const float*)d_in[0];
    const int* src0  = (const int*)d_in[1];
    const int* dst0  = (const int*)d_in[2];
    const int* src1  = (const int*)d_in[3];
    const int* dst1  = (const int*)d_in[4];
    const int* src2  = (const int*)d_in[5];
    const int* dst2  = (const int*)d_in[6];
    const float* ws0 = (const float*)d_in[7];
    const float* wn0 = (const float*)d_in[8];
    const float* b0  = (const float*)d_in[9];
    const float* ws1 = (const float*)d_in[10];
    const float* wn1 = (const float*)d_in[11];
    const float* b1  = (const float*)d_in[12];
    const float* ws2 = (const float*)d_in[13];
    const float* wn2 = (const float*)d_in[14];
    const float* b2  = (const float*)d_in[15];

    const int E0 = in_sizes[1];
    const int E1 = in_sizes[3];
    const int E2 = in_sizes[5];

    float *agg0, *h1, *agg1, *h2, *agg2;
    cudaGetSymbolAddress((void**)&agg0, g_agg0);
    cudaGetSymbolAddress((void**)&h1,   g_h1);
    cudaGetSymbolAddress((void**)&agg1, g_agg1);
    cudaGetSymbolAddress((void**)&h2,   g_h2);
    cudaGetSymbolAddress((void**)&agg2, g_agg2);

    float* out = (float*)d_out;

    // 1) Zero accumulators
    {
        int n4;
        n4 = N1 * DIM / 4;
        zero_kernel<<<(n4 + 255) / 256 < 8192 ? (n4 + 255) / 256 : 8192, 256>>>((float4*)agg0, n4);
        n4 = N2 * DIM / 4;
        zero_kernel<<<(n4 + 255) / 256, 256>>>((float4*)agg1, n4);
        n4 = N3 * DIM / 4;
        zero_kernel<<<(n4 + 255) / 256, 256>>>((float4*)agg2, n4);
    }

    // 2) Layer 0: scatter + TC GEMM + relu
    {
        int warps = (E0 + EDGES_PER_WARP - 1) / EDGES_PER_WARP;
        scatter_add_kernel<<<(warps + 7) / 8, 256>>>(x, src0, dst0, agg0, E0);
        dim3 grid((N1 + BM - 1) / BM, DIM / BN);
        sage_gemm_tc_kernel<<<grid, 256>>>(x, agg0, ws0, wn0, b0, h1, N1, 1);
    }

    // 3) Layer 1
    {
        int warps = (E1 + EDGES_PER_WARP - 1) / EDGES_PER_WARP;
        scatter_add_kernel<<<(warps + 7) / 8, 256>>>(h1, src1, dst1, agg1, E1);
        dim3 grid((N2 + BM - 1) / BM, DIM / BN);
        sage_gemm_tc_kernel<<<grid, 256>>>(h1, agg1, ws1, wn1, b1, h2, N2, 1);
    }

    // 4) Layer 2 (output, N=47, no relu)
    {
        int warps = (E2 + EDGES_PER_WARP - 1) / EDGES_PER_WARP;
        scatter_add_kernel<<<(warps + 7) / 8, 256>>>(h2, src2, dst2, agg2, E2);
        sage_out_kernel<<<N3, 64>>>(h2, agg2, ws2, wn2, b2, out);
    }
}

// round 7
// speedup vs baseline: 1.7028x; 1.1430x over previous
#include <cuda_runtime.h>
#include <cuda_bf16.h>
#include <cstdint>

// ---------------------------------------------------------------------------
// Problem constants (fixed shapes from setup_inputs)
// ---------------------------------------------------------------------------
#define N0 400000
#define N1 100000
#define N2 25000
#define N3 6250
#define DIM 256          // D == H == 256
#define COUT 47
#define E0MAX 1600000

// ---------------------------------------------------------------------------
// Scratch (device globals; allocation-free)
// ---------------------------------------------------------------------------
__device__ float g_agg0[(size_t)N1 * DIM];   // 102.4 MB
__device__ float g_h1  [(size_t)N1 * DIM];   // 102.4 MB
__device__ float g_agg1[(size_t)N2 * DIM];   //  25.6 MB
__device__ float g_h2  [(size_t)N2 * DIM];   //  25.6 MB
__device__ float g_agg2[(size_t)N3 * DIM];   //   6.4 MB
__device__ int   g_deg[N1];                  // degree histogram
__device__ int   g_off[N1 + 1];              // CSR row offsets
__device__ int   g_pos[N1];                  // fill cursors
__device__ int   g_csr[E0MAX];               // src node per CSR slot

// ---------------------------------------------------------------------------
// CSR build: histogram -> exclusive scan -> cursor fill
// ---------------------------------------------------------------------------
__global__ void zero_int_kernel(int* __restrict__ p, int n) {
    int i = blockIdx.x * blockDim.x + threadIdx.x;
    if (i < n) p[i] = 0;
}

__global__ void hist_kernel(const int* __restrict__ dst, int* __restrict__ deg, int E) {
    int i = blockIdx.x * blockDim.x + threadIdx.x;
    if (i < E) atomicAdd(&deg[dst[i]], 1);
}

// Single-block exclusive scan over n <= 131072 elements (1024 thr x chunk).
__global__ __launch_bounds__(1024)
void scan_kernel(const int* __restrict__ deg, int* __restrict__ off, int n) {
    __shared__ int partial[1024];
    int tid = threadIdx.x;
    int chunk = (n + 1023) >> 10;
    int base = tid * chunk;
    int s = 0;
    for (int i = 0; i < chunk; ++i) {
        int idx = base + i;
        if (idx < n) s += deg[idx];
    }
    partial[tid] = s;
    __syncthreads();
    for (int d = 1; d < 1024; d <<= 1) {
        int v = (tid >= d) ? partial[tid - d] : 0;
        __syncthreads();
        partial[tid] += v;
        __syncthreads();
    }
    int run = (tid == 0) ? 0 : partial[tid - 1];
    for (int i = 0; i < chunk; ++i) {
        int idx = base + i;
        if (idx < n) { off[idx] = run; run += deg[idx]; }
    }
    if (tid == 1023) off[n] = partial[1023];
}

__global__ void copy_int_kernel(const int* __restrict__ a, int* __restrict__ b, int n) {
    int i = blockIdx.x * blockDim.x + threadIdx.x;
    if (i < n) b[i] = a[i];
}

__global__ void fill_kernel(const int* __restrict__ src, const int* __restrict__ dst,
                            int* __restrict__ pos, int* __restrict__ csr, int E) {
    int i = blockIdx.x * blockDim.x + threadIdx.x;
    if (i < E) {
        int slot = atomicAdd(&pos[dst[i]], 1);
        csr[slot] = src[i];
    }
}

// ---------------------------------------------------------------------------
// CSR aggregation: one warp per dst row. Accumulate all neighbor rows in
// registers (8 f32/lane), single streaming store. No RMW traffic at all.
// ---------------------------------------------------------------------------
__global__ void csr_aggregate_kernel(const float* __restrict__ X,
                                     const int* __restrict__ csr,
                                     const int* __restrict__ off,
                                     float* __restrict__ agg, int nrows) {
    int row = blockIdx.x * (blockDim.x >> 5) + (threadIdx.x >> 5);
    if (row >= nrows) return;
    int lane = threadIdx.x & 31;
    int beg = off[row], end = off[row + 1];

    float4 a0 = make_float4(0.f, 0.f, 0.f, 0.f);
    float4 a1 = make_float4(0.f, 0.f, 0.f, 0.f);

    int e = beg;
    for (; e + 4 <= end; e += 4) {
        int s0 = __ldg(&csr[e + 0]);
        int s1 = __ldg(&csr[e + 1]);
        int s2 = __ldg(&csr[e + 2]);
        int s3 = __ldg(&csr[e + 3]);
        const float4* p0 = (const float4*)(X + (size_t)s0 * DIM);
        const float4* p1 = (const float4*)(X + (size_t)s1 * DIM);
        const float4* p2 = (const float4*)(X + (size_t)s2 * DIM);
        const float4* p3 = (const float4*)(X + (size_t)s3 * DIM);
        float4 u0 = __ldg(p0 + lane), w0 = __ldg(p0 + lane + 32);
        float4 u1 = __ldg(p1 + lane), w1 = __ldg(p1 + lane + 32);
        float4 u2 = __ldg(p2 + lane), w2 = __ldg(p2 + lane + 32);
        float4 u3 = __ldg(p3 + lane), w3 = __ldg(p3 + lane + 32);
        a0.x += u0.x + u1.x + u2.x + u3.x;
        a0.y += u0.y + u1.y + u2.y + u3.y;
        a0.z += u0.z + u1.z + u2.z + u3.z;
        a0.w += u0.w + u1.w + u2.w + u3.w;
        a1.x += w0.x + w1.x + w2.x + w3.x;
        a1.y += w0.y + w1.y + w2.y + w3.y;
        a1.z += w0.z + w1.z + w2.z + w3.z;
        a1.w += w0.w + w1.w + w2.w + w3.w;
    }
    for (; e < end; ++e) {
        int s = __ldg(&csr[e]);
        const float4* p = (const float4*)(X + (size_t)s * DIM);
        float4 u = __ldg(p + lane), w = __ldg(p + lane + 32);
        a0.x += u.x; a0.y += u.y; a0.z += u.z; a0.w += u.w;
        a1.x += w.x; a1.y += w.y; a1.z += w.z; a1.w += w.w;
    }
    float4* ap = (float4*)(agg + (size_t)row * DIM);
    ap[lane]      = a0;
    ap[lane + 32] = a1;
}

// ---------------------------------------------------------------------------
// TF32 tensor-core fused dual-A GEMM:
//   C = relu?( A1 @ B1 + A2 @ B2 + bias )
// Block tile 128x128, BK=16, 256 threads = 8 warps (2M x 4N),
// warp tile 64x32, mma.sync m16n8k8 tf32.
// ---------------------------------------------------------------------------
#define BM 128
#define BN 128
#define BK 16
#define PAD 8

__device__ __forceinline__ float f2tf32(float x) {
    uint32_t r;
    asm("cvt.rna.tf32.f32 %0, %1;" : "=r"(r) : "f"(x));
    return __uint_as_float(r);
}

__device__ __forceinline__ void mma_tf32(float c[4], const uint32_t a[4], const uint32_t b[2]) {
    asm volatile(
        "mma.sync.aligned.m16n8k8.row.col.f32.tf32.tf32.f32 "
        "{%0,%1,%2,%3}, {%4,%5,%6,%7}, {%8,%9}, {%0,%1,%2,%3};"
        : "+f"(c[0]), "+f"(c[1]), "+f"(c[2]), "+f"(c[3])
        : "r"(a[0]), "r"(a[1]), "r"(a[2]), "r"(a[3]), "r"(b[0]), "r"(b[1]));
}

__global__ __launch_bounds__(256, 2)
void sage_gemm_tc_kernel(const float* __restrict__ A1, const float* __restrict__ A2,
                         const float* __restrict__ B1, const float* __restrict__ B2,
                         const float* __restrict__ bias, float* __restrict__ C,
                         int M, int relu) {
    __shared__ float As[BK][BM + PAD];
    __shared__ float Bs[BK][BN + PAD];

    const int tid  = threadIdx.x;
    const int lane = tid & 31;
    const int wid  = tid >> 5;
    const int tg   = lane & 3;
    const int gid  = lane >> 2;
    const int wr   = wid >> 2;
    const int wc   = wid & 3;
    const int wm   = wr * 64;
    const int wn   = wc * 32;
    const int m0   = blockIdx.x * BM;
    const int n0   = blockIdx.y * BN;
    const int K = DIM, N = DIM;

    float acc[4][4][4];
#pragma unroll
    for (int i = 0; i < 4; ++i)
#pragma unroll
        for (int j = 0; j < 4; ++j)
#pragma unroll
            for (int r = 0; r < 4; ++r) acc[i][j][r] = 0.f;

#pragma unroll 1
    for (int sSel = 0; sSel < 2; ++sSel) {
        const float* __restrict__ A = sSel ? A2 : A1;
        const float* __restrict__ B = sSel ? B2 : B1;
#pragma unroll 1
        for (int kt = 0; kt < K; kt += BK) {
#pragma unroll
            for (int i = 0; i < 2; ++i) {
                int id = tid + i * 256;
                int row = id >> 2;
                int kc4 = id & 3;
                float4 v;
                int gr = m0 + row;
                if (gr < M) v = *(const float4*)&A[(size_t)gr * K + kt + kc4 * 4];
                else        v = make_float4(0.f, 0.f, 0.f, 0.f);
                As[kc4 * 4 + 0][row] = f2tf32(v.x);
                As[kc4 * 4 + 1][row] = f2tf32(v.y);
                As[kc4 * 4 + 2][row] = f2tf32(v.z);
                As[kc4 * 4 + 3][row] = f2tf32(v.w);
            }
#pragma unroll
            for (int i = 0; i < 2; ++i) {
                int id = tid + i * 256;
                int krow = id >> 5;
                int nc4 = id & 31;
                float4 v = *(const float4*)&B[(size_t)(kt + krow) * N + n0 + nc4 * 4];
                float4 t;
                t.x = f2tf32(v.x); t.y = f2tf32(v.y);
                t.z = f2tf32(v.z); t.w = f2tf32(v.w);
                *(float4*)&Bs[krow][nc4 * 4] = t;
            }
            __syncthreads();

#pragma unroll
            for (int kk = 0; kk < BK; kk += 8) {
                uint32_t af[4][4], bf[4][2];
#pragma unroll
                for (int i = 0; i < 4; ++i) {
                    int mr = wm + i * 16 + gid;
                    af[i][0] = __float_as_uint(As[kk + tg][mr]);
                    af[i][1] = __float_as_uint(As[kk + tg][mr + 8]);
                    af[i][2] = __float_as_uint(As[kk + tg + 4][mr]);
                    af[i][3] = __float_as_uint(As[kk + tg + 4][mr + 8]);
                }
#pragma unroll
                for (int j = 0; j < 4; ++j) {
                    int nc = wn + j * 8 + gid;
                    bf[j][0] = __float_as_uint(Bs[kk + tg][nc]);
                    bf[j][1] = __float_as_uint(Bs[kk + tg + 4][nc]);
                }
#pragma unroll
                for (int i = 0; i < 4; ++i)
#pragma unroll
                    for (int j = 0; j < 4; ++j)
                        mma_tf32(acc[i][j], af[i], bf[j]);
            }
            __syncthreads();
        }
    }

#pragma unroll
    for (int i = 0; i < 4; ++i) {
#pragma unroll
        for (int rh = 0; rh < 2; ++rh) {
            int row = m0 + wm + i * 16 + gid + rh * 8;
            if (row >= M) continue;
#pragma unroll
            for (int j = 0; j < 4; ++j) {
                int col = n0 + wn + j * 8 + tg * 2;
                float2 v;
                v.x = acc[i][j][rh * 2 + 0] + bias[col + 0];
                v.y = acc[i][j][rh * 2 + 1] + bias[col + 1];
                if (relu) { v.x = fmaxf(v.x, 0.f); v.y = fmaxf(v.y, 0.f); }
                *(float2*)&C[(size_t)row * N + col] = v;
            }
        }
    }
}

// ---------------------------------------------------------------------------
// Final layer: out[M, 47] = h @ Wself + agg @ Wneigh + bias  (no relu)
// ---------------------------------------------------------------------------
__global__ __launch_bounds__(64)
void sage_out_kernel(const float* __restrict__ h, const float* __restrict__ agg,
                     const float* __restrict__ Ws, const float* __restrict__ Wn,
                     const float* __restrict__ bias, float* __restrict__ out) {
    int row = blockIdx.x;
    __shared__ float sh[DIM];
    __shared__ float sa[DIM];
    for (int i = threadIdx.x; i < DIM; i += 64) {
        sh[i] = h[(size_t)row * DIM + i];
        sa[i] = agg[(size_t)row * DIM + i];
    }
    __syncthreads();
    int j = threadIdx.x;
    if (j < COUT) {
        float acc = bias[j];
#pragma unroll 4
        for (int k = 0; k < DIM; ++k) {
            acc = fmaf(sh[k], Ws[k * COUT + j], acc);
            acc = fmaf(sa[k], Wn[k * COUT + j], acc);
        }
        out[(size_t)row * COUT + j] = acc;
    }
}

// ---------------------------------------------------------------------------
// Host-side helper: build CSR + aggregate for one layer
// ---------------------------------------------------------------------------
static void build_and_aggregate(const float* X, const int* src, const int* dst,
                                float* agg, int E, int nrows,
                                int* deg, int* off, int* pos, int* csr) {
    zero_int_kernel<<<(nrows + 255) / 256, 256>>>(deg, nrows);
    hist_kernel<<<(E + 255) / 256, 256>>>(dst, deg, E);
    scan_kernel<<<1, 1024>>>(deg, off, nrows);
    copy_int_kernel<<<(nrows + 255) / 256, 256>>>(off, pos, nrows);
    fill_kernel<<<(E + 255) / 256, 256>>>(src, dst, pos, csr, E);
    csr_aggregate_kernel<<<(nrows + 7) / 8, 256>>>(X, csr, off, agg, nrows);
}

// ---------------------------------------------------------------------------
// Launch
// ---------------------------------------------------------------------------
extern "C" void kernel_launch(void* const* d_in, const int* in_sizes, int n_in,
                              void* d_out, int out_size) {
    const float* x   = (const float*)d_in[0];
    const int* src0  = (const int*)d_in[1];
    const int* dst0  = (const int*)d_in[2];
    const int* src1  = (const int*)d_in[3];
    const int* dst1  = (const int*)d_in[4];
    const int* src2  = (const int*)d_in[5];
    const int* dst2  = (const int*)d_in[6];
    const float* ws0 = (const float*)d_in[7];
    const float* wn0 = (const float*)d_in[8];
    const float* b0  = (const float*)d_in[9];
    const float* ws1 = (const float*)d_in[10];
    const float* wn1 = (const float*)d_in[11];
    const float* b1  = (const float*)d_in[12];
    const float* ws2 = (const float*)d_in[13];
    const float* wn2 = (const float*)d_in[14];
    const float* b2  = (const float*)d_in[15];

    const int E0 = in_sizes[1];
    const int E1 = in_sizes[3];
    const int E2 = in_sizes[5];

    float *agg0, *h1, *agg1, *h2, *agg2;
    int *deg, *off, *pos, *csr;
    cudaGetSymbolAddress((void**)&agg0, g_agg0);
    cudaGetSymbolAddress((void**)&h1,   g_h1);
    cudaGetSymbolAddress((void**)&agg1, g_agg1);
    cudaGetSymbolAddress((void**)&h2,   g_h2);
    cudaGetSymbolAddress((void**)&agg2, g_agg2);
    cudaGetSymbolAddress((void**)&deg,  g_deg);
    cudaGetSymbolAddress((void**)&off,  g_off);
    cudaGetSymbolAddress((void**)&pos,  g_pos);
    cudaGetSymbolAddress((void**)&csr,  g_csr);

    float* out = (float*)d_out;

    // Layer 0
    build_and_aggregate(x, src0, dst0, agg0, E0, N1, deg, off, pos, csr);
    {
        dim3 grid((N1 + BM - 1) / BM, DIM / BN);
        sage_gemm_tc_kernel<<<grid, 256>>>(x, agg0, ws0, wn0, b0, h1, N1, 1);
    }

    // Layer 1
    build_and_aggregate(h1, src1, dst1, agg1, E1, N2, deg, off, pos, csr);
    {
        dim3 grid((N2 + BM - 1) / BM, DIM / BN);
        sage_gemm_tc_kernel<<<grid, 256>>>(h1, agg1, ws1, wn1, b1, h2, N2, 1);
    }

    // Layer 2 (output, N=47, no relu)
    build_and_aggregate(h2, src2, dst2, agg2, E2, N3, deg, off, pos, csr);
    sage_out_kernel<<<N3, 64>>>(h2, agg2, ws2, wn2, b2, out);
}

// round 10
// speedup vs baseline: 1.8125x; 1.0644x over previous
#include <cuda_runtime.h>
#include <cuda_bf16.h>
#include <cstdint>

// ---------------------------------------------------------------------------
// Problem constants (fixed shapes from setup_inputs)
// ---------------------------------------------------------------------------
#define N0 400000
#define N1 100000
#define N2 25000
#define N3 6250
#define DIM 256          // D == H == 256
#define COUT 47
#define E0MAX 1600000

// ---------------------------------------------------------------------------
// Scratch (device globals; allocation-free)
// ---------------------------------------------------------------------------
__device__ float g_agg0[(size_t)N1 * DIM];   // 102.4 MB
__device__ float g_h1  [(size_t)N1 * DIM];   // 102.4 MB
__device__ float g_agg1[(size_t)N2 * DIM];   //  25.6 MB
__device__ float g_h2  [(size_t)N2 * DIM];   //  25.6 MB
__device__ float g_agg2[(size_t)N3 * DIM];   //   6.4 MB
__device__ int   g_deg[N1];                  // degree histogram
__device__ int   g_off[N1 + 1];              // CSR row offsets
__device__ int   g_pos[N1];                  // fill cursors
__device__ int   g_csr[E0MAX];               // src node per CSR slot

// ---------------------------------------------------------------------------
// CSR build: histogram -> exclusive scan -> cursor fill
// ---------------------------------------------------------------------------
__global__ void zero_int_kernel(int* __restrict__ p, int n) {
    int i = blockIdx.x * blockDim.x + threadIdx.x;
    if (i < n) p[i] = 0;
}

__global__ void hist_kernel(const int* __restrict__ dst, int* __restrict__ deg, int E) {
    int i = blockIdx.x * blockDim.x + threadIdx.x;
    if (i < E) atomicAdd(&deg[dst[i]], 1);
}

// Single-block exclusive scan over n <= 131072 elements (1024 thr x chunk).
__global__ __launch_bounds__(1024)
void scan_kernel(const int* __restrict__ deg, int* __restrict__ off, int n) {
    __shared__ int partial[1024];
    int tid = threadIdx.x;
    int chunk = (n + 1023) >> 10;
    int base = tid * chunk;
    int s = 0;
    for (int i = 0; i < chunk; ++i) {
        int idx = base + i;
        if (idx < n) s += deg[idx];
    }
    partial[tid] = s;
    __syncthreads();
    for (int d = 1; d < 1024; d <<= 1) {
        int v = (tid >= d) ? partial[tid - d] : 0;
        __syncthreads();
        partial[tid] += v;
        __syncthreads();
    }
    int run = (tid == 0) ? 0 : partial[tid - 1];
    for (int i = 0; i < chunk; ++i) {
        int idx = base + i;
        if (idx < n) { off[idx] = run; run += deg[idx]; }
    }
    if (tid == 1023) off[n] = partial[1023];
}

__global__ void copy_int_kernel(const int* __restrict__ a, int* __restrict__ b, int n) {
    int i = blockIdx.x * blockDim.x + threadIdx.x;
    if (i < n) b[i] = a[i];
}

__global__ void fill_kernel(const int* __restrict__ src, const int* __restrict__ dst,
                            int* __restrict__ pos, int* __restrict__ csr, int E) {
    int i = blockIdx.x * blockDim.x + threadIdx.x;
    if (i < E) {
        int slot = atomicAdd(&pos[dst[i]], 1);
        csr[slot] = src[i];
    }
}

// ---------------------------------------------------------------------------
// CSR aggregation: one warp per dst row. Accumulate all neighbor rows in
// registers (8 f32/lane), single streaming store. No RMW traffic at all.
// ---------------------------------------------------------------------------
__global__ void csr_aggregate_kernel(const float* __restrict__ X,
                                     const int* __restrict__ csr,
                                     const int* __restrict__ off,
                                     float* __restrict__ agg, int nrows) {
    int row = blockIdx.x * (blockDim.x >> 5) + (threadIdx.x >> 5);
    if (row >= nrows) return;
    int lane = threadIdx.x & 31;
    int beg = off[row], end = off[row + 1];

    float4 a0 = make_float4(0.f, 0.f, 0.f, 0.f);
    float4 a1 = make_float4(0.f, 0.f, 0.f, 0.f);

    int e = beg;
    for (; e + 4 <= end; e += 4) {
        int s0 = __ldg(&csr[e + 0]);
        int s1 = __ldg(&csr[e + 1]);
        int s2 = __ldg(&csr[e + 2]);
        int s3 = __ldg(&csr[e + 3]);
        const float4* p0 = (const float4*)(X + (size_t)s0 * DIM);
        const float4* p1 = (const float4*)(X + (size_t)s1 * DIM);
        const float4* p2 = (const float4*)(X + (size_t)s2 * DIM);
        const float4* p3 = (const float4*)(X + (size_t)s3 * DIM);
        float4 u0 = __ldg(p0 + lane), w0 = __ldg(p0 + lane + 32);
        float4 u1 = __ldg(p1 + lane), w1 = __ldg(p1 + lane + 32);
        float4 u2 = __ldg(p2 + lane), w2 = __ldg(p2 + lane + 32);
        float4 u3 = __ldg(p3 + lane), w3 = __ldg(p3 + lane + 32);
        a0.x += u0.x + u1.x + u2.x + u3.x;
        a0.y += u0.y + u1.y + u2.y + u3.y;
        a0.z += u0.z + u1.z + u2.z + u3.z;
        a0.w += u0.w + u1.w + u2.w + u3.w;
        a1.x += w0.x + w1.x + w2.x + w3.x;
        a1.y += w0.y + w1.y + w2.y + w3.y;
        a1.z += w0.z + w1.z + w2.z + w3.z;
        a1.w += w0.w + w1.w + w2.w + w3.w;
    }
    for (; e < end; ++e) {
        int s = __ldg(&csr[e]);
        const float4* p = (const float4*)(X + (size_t)s * DIM);
        float4 u = __ldg(p + lane), w = __ldg(p + lane + 32);
        a0.x += u.x; a0.y += u.y; a0.z += u.z; a0.w += u.w;
        a1.x += w.x; a1.y += w.y; a1.z += w.z; a1.w += w.w;
    }
    float4* ap = (float4*)(agg + (size_t)row * DIM);
    ap[lane]      = a0;
    ap[lane + 32] = a1;
}

// ---------------------------------------------------------------------------
// TF32 tensor-core fused dual-A GEMM, double-buffered pipeline:
//   C = relu?( A1 @ B1 + A2 @ B2 + bias )
// Virtual K=512 (32 tiles of BK=16); prefetch tile t+1 global->regs while
// computing tile t from smem. cvt.rna.tf32 applied at smem-store time
// (unbiased rounding — required for accuracy; overlapped with load latency).
// ---------------------------------------------------------------------------
#define BM 128
#define BN 128
#define BK 16
#define PAD 8

__device__ __forceinline__ float f2tf32(float x) {
    uint32_t r;
    asm("cvt.rna.tf32.f32 %0, %1;" : "=r"(r) : "f"(x));
    return __uint_as_float(r);
}

__device__ __forceinline__ void mma_tf32(float c[4], const uint32_t a[4], const uint32_t b[2]) {
    asm volatile(
        "mma.sync.aligned.m16n8k8.row.col.f32.tf32.tf32.f32 "
        "{%0,%1,%2,%3}, {%4,%5,%6,%7}, {%8,%9}, {%0,%1,%2,%3};"
        : "+f"(c[0]), "+f"(c[1]), "+f"(c[2]), "+f"(c[3])
        : "r"(a[0]), "r"(a[1]), "r"(a[2]), "r"(a[3]), "r"(b[0]), "r"(b[1]));
}

__global__ __launch_bounds__(256, 2)
void sage_gemm_tc_kernel(const float* __restrict__ A1, const float* __restrict__ A2,
                         const float* __restrict__ B1, const float* __restrict__ B2,
                         const float* __restrict__ bias, float* __restrict__ C,
                         int M, int relu) {
    __shared__ float As[2][BK][BM + PAD];
    __shared__ float Bs[2][BK][BN + PAD];

    const int tid  = threadIdx.x;
    const int lane = tid & 31;
    const int wid  = tid >> 5;
    const int tg   = lane & 3;
    const int gid  = lane >> 2;
    const int wm   = (wid >> 2) * 64;
    const int wn   = (wid & 3) * 32;
    const int m0   = blockIdx.x * BM;
    const int n0   = blockIdx.y * BN;
    const int K = DIM, N = DIM;
    const int T = 2 * (DIM / BK);          // 32 tiles

    // per-thread staging indices (2 float4 each for A and B)
    const int arow0 = (tid + 0)   >> 2, akc0 = (tid + 0)   & 3;
    const int arow1 = (tid + 256) >> 2, akc1 = (tid + 256) & 3;
    const int bkr0  = (tid + 0)   >> 5, bnc0 = (tid + 0)   & 31;
    const int bkr1  = (tid + 256) >> 5, bnc1 = (tid + 256) & 31;

    float acc[4][4][4];
#pragma unroll
    for (int i = 0; i < 4; ++i)
#pragma unroll
        for (int j = 0; j < 4; ++j)
#pragma unroll
            for (int r = 0; r < 4; ++r) acc[i][j][r] = 0.f;

    float4 pa0, pa1, pb0, pb1;

    auto load_tile = [&](int t) {
        const float* __restrict__ A = (t < T / 2) ? A1 : A2;
        const float* __restrict__ B = (t < T / 2) ? B1 : B2;
        int kt = (t & (T / 2 - 1)) * BK;
        int gr0 = m0 + arow0, gr1 = m0 + arow1;
        pa0 = (gr0 < M) ? *(const float4*)&A[(size_t)gr0 * K + kt + akc0 * 4]
                        : make_float4(0.f, 0.f, 0.f, 0.f);
        pa1 = (gr1 < M) ? *(const float4*)&A[(size_t)gr1 * K + kt + akc1 * 4]
                        : make_float4(0.f, 0.f, 0.f, 0.f);
        pb0 = *(const float4*)&B[(size_t)(kt + bkr0) * N + n0 + bnc0 * 4];
        pb1 = *(const float4*)&B[(size_t)(kt + bkr1) * N + n0 + bnc1 * 4];
    };

    auto store_tile = [&](int s) {
        As[s][akc0 * 4 + 0][arow0] = f2tf32(pa0.x);
        As[s][akc0 * 4 + 1][arow0] = f2tf32(pa0.y);
        As[s][akc0 * 4 + 2][arow0] = f2tf32(pa0.z);
        As[s][akc0 * 4 + 3][arow0] = f2tf32(pa0.w);
        As[s][akc1 * 4 + 0][arow1] = f2tf32(pa1.x);
        As[s][akc1 * 4 + 1][arow1] = f2tf32(pa1.y);
        As[s][akc1 * 4 + 2][arow1] = f2tf32(pa1.z);
        As[s][akc1 * 4 + 3][arow1] = f2tf32(pa1.w);
        float4 tb0, tb1;
        tb0.x = f2tf32(pb0.x); tb0.y = f2tf32(pb0.y);
        tb0.z = f2tf32(pb0.z); tb0.w = f2tf32(pb0.w);
        tb1.x = f2tf32(pb1.x); tb1.y = f2tf32(pb1.y);
        tb1.z = f2tf32(pb1.z); tb1.w = f2tf32(pb1.w);
        *(float4*)&Bs[s][bkr0][bnc0 * 4] = tb0;
        *(float4*)&Bs[s][bkr1][bnc1 * 4] = tb1;
    };

    // prologue
    load_tile(0);
    store_tile(0);
    __syncthreads();

#pragma unroll 1
    for (int t = 0; t < T; ++t) {
        if (t + 1 < T) load_tile(t + 1);
        const int st = t & 1;
#pragma unroll
        for (int kk = 0; kk < BK; kk += 8) {
            uint32_t af[4][4], bf[4][2];
#pragma unroll
            for (int i = 0; i < 4; ++i) {
                int mr = wm + i * 16 + gid;
                af[i][0] = __float_as_uint(As[st][kk + tg][mr]);
                af[i][1] = __float_as_uint(As[st][kk + tg][mr + 8]);
                af[i][2] = __float_as_uint(As[st][kk + tg + 4][mr]);
                af[i][3] = __float_as_uint(As[st][kk + tg + 4][mr + 8]);
            }
#pragma unroll
            for (int j = 0; j < 4; ++j) {
                int nc = wn + j * 8 + gid;
                bf[j][0] = __float_as_uint(Bs[st][kk + tg][nc]);
                bf[j][1] = __float_as_uint(Bs[st][kk + tg + 4][nc]);
            }
#pragma unroll
            for (int i = 0; i < 4; ++i)
#pragma unroll
                for (int j = 0; j < 4; ++j)
                    mma_tf32(acc[i][j], af[i], bf[j]);
        }
        if (t + 1 < T) {
            store_tile((t + 1) & 1);
            __syncthreads();
        }
    }

    // epilogue: bias (+relu), float2 stores
#pragma unroll
    for (int i = 0; i < 4; ++i) {
#pragma unroll
        for (int rh = 0; rh < 2; ++rh) {
            int row = m0 + wm + i * 16 + gid + rh * 8;
            if (row >= M) continue;
#pragma unroll
            for (int j = 0; j < 4; ++j) {
                int col = n0 + wn + j * 8 + tg * 2;
                float2 v;
                v.x = acc[i][j][rh * 2 + 0] + bias[col + 0];
                v.y = acc[i][j][rh * 2 + 1] + bias[col + 1];
                if (relu) { v.x = fmaxf(v.x, 0.f); v.y = fmaxf(v.y, 0.f); }
                *(float2*)&C[(size_t)row * N + col] = v;
            }
        }
    }
}

// ---------------------------------------------------------------------------
// Final layer: out[M, 47] = h @ Wself + agg @ Wneigh + bias  (no relu)
// ---------------------------------------------------------------------------
__global__ __launch_bounds__(64)
void sage_out_kernel(const float* __restrict__ h, const float* __restrict__ agg,
                     const float* __restrict__ Ws, const float* __restrict__ Wn,
                     const float* __restrict__ bias, float* __restrict__ out) {
    int row = blockIdx.x;
    __shared__ float sh[DIM];
    __shared__ float sa[DIM];
    for (int i = threadIdx.x; i < DIM; i += 64) {
        sh[i] = h[(size_t)row * DIM + i];
        sa[i] = agg[(size_t)row * DIM + i];
    }
    __syncthreads();
    int j = threadIdx.x;
    if (j < COUT) {
        float acc = bias[j];
#pragma unroll 4
        for (int k = 0; k < DIM; ++k) {
            acc = fmaf(sh[k], Ws[k * COUT + j], acc);
            acc = fmaf(sa[k], Wn[k * COUT + j], acc);
        }
        out[(size_t)row * COUT + j] = acc;
    }
}

// ---------------------------------------------------------------------------
// Host-side helper: build CSR + aggregate for one layer
// ---------------------------------------------------------------------------
static void build_and_aggregate(const float* X, const int* src, const int* dst,
                                float* agg, int E, int nrows,
                                int* deg, int* off, int* pos, int* csr) {
    zero_int_kernel<<<(nrows + 255) / 256, 256>>>(deg, nrows);
    hist_kernel<<<(E + 255) / 256, 256>>>(dst, deg, E);
    scan_kernel<<<1, 1024>>>(deg, off, nrows);
    copy_int_kernel<<<(nrows + 255) / 256, 256>>>(off, pos, nrows);
    fill_kernel<<<(E + 255) / 256, 256>>>(src, dst, pos, csr, E);
    csr_aggregate_kernel<<<(nrows + 7) / 8, 256>>>(X, csr, off, agg, nrows);
}

// ---------------------------------------------------------------------------
// Launch
// ---------------------------------------------------------------------------
extern "C" void kernel_launch(void* const* d_in, const int* in_sizes, int n_in,
                              void* d_out, int out_size) {
    const float* x   = (const float*)d_in[0];
    const int* src0  = (const int*)d_in[1];
    const int* dst0  = (const int*)d_in[2];
    const int* src1  = (const int*)d_in[3];
    const int* dst1  = (const int*)d_in[4];
    const int* src2  = (const int*)d_in[5];
    const int* dst2  = (const int*)d_in[6];
    const float* ws0 = (const float*)d_in[7];
    const float* wn0 = (const float*)d_in[8];
    const float* b0  = (const float*)d_in[9];
    const float* ws1 = (const float*)d_in[10];
    const float* wn1 = (const float*)d_in[11];
    const float* b1  = (const float*)d_in[12];
    const float* ws2 = (const float*)d_in[13];
    const float* wn2 = (const float*)d_in[14];
    const float* b2  = (const float*)d_in[15];

    const int E0 = in_sizes[1];
    const int E1 = in_sizes[3];
    const int E2 = in_sizes[5];

    float *agg0, *h1, *agg1, *h2, *agg2;
    int *deg, *off, *pos, *csr;
    cudaGetSymbolAddress((void**)&agg0, g_agg0);
    cudaGetSymbolAddress((void**)&h1,   g_h1);
    cudaGetSymbolAddress((void**)&agg1, g_agg1);
    cudaGetSymbolAddress((void**)&h2,   g_h2);
    cudaGetSymbolAddress((void**)&agg2, g_agg2);
    cudaGetSymbolAddress((void**)&deg,  g_deg);
    cudaGetSymbolAddress((void**)&off,  g_off);
    cudaGetSymbolAddress((void**)&pos,  g_pos);
    cudaGetSymbolAddress((void**)&csr,  g_csr);

    float* out = (float*)d_out;

    // Layer 0
    build_and_aggregate(x, src0, dst0, agg0, E0, N1, deg, off, pos, csr);
    {
        dim3 grid((N1 + BM - 1) / BM, DIM / BN);
        sage_gemm_tc_kernel<<<grid, 256>>>(x, agg0, ws0, wn0, b0, h1, N1, 1);
    }

    // Layer 1
    build_and_aggregate(h1, src1, dst1, agg1, E1, N2, deg, off, pos, csr);
    {
        dim3 grid((N2 + BM - 1) / BM, DIM / BN);
        sage_gemm_tc_kernel<<<grid, 256>>>(h1, agg1, ws1, wn1, b1, h2, N2, 1);
    }

    // Layer 2 (output, N=47, no relu)
    build_and_aggregate(h2, src2, dst2, agg2, E2, N3, deg, off, pos, csr);
    sage_out_kernel<<<N3, 64>>>(h2, agg2, ws2, wn2, b2, out);
}

// round 11
// speedup vs baseline: 1.8403x; 1.0153x over previous
#include <cuda_runtime.h>
#include <cuda_bf16.h>
#include <cstdint>

// ---------------------------------------------------------------------------
// Problem constants (fixed shapes from setup_inputs)
// ---------------------------------------------------------------------------
#define N0 400000
#define N1 100000
#define N2 25000
#define N3 6250
#define DIM 256          // D == H == 256
#define COUT 47
#define E0MAX 1600000

// ---------------------------------------------------------------------------
// Scratch (device globals; allocation-free)
// ---------------------------------------------------------------------------
__device__ float g_agg0[(size_t)N1 * DIM];   // 102.4 MB
__device__ float g_h1  [(size_t)N1 * DIM];   // 102.4 MB
__device__ float g_agg1[(size_t)N2 * DIM];   //  25.6 MB
__device__ float g_h2  [(size_t)N2 * DIM];   //  25.6 MB
__device__ float g_agg2[(size_t)N3 * DIM];   //   6.4 MB
__device__ int   g_deg[N1];                  // degree histogram
__device__ int   g_off[N1 + 1];              // CSR row offsets
__device__ int   g_pos[N1];                  // fill cursors
__device__ int   g_csr[E0MAX];               // src node per CSR slot

// ---------------------------------------------------------------------------
// CSR build: histogram -> exclusive scan -> cursor fill
// ---------------------------------------------------------------------------
__global__ void zero_int_kernel(int* __restrict__ p, int n) {
    int i = blockIdx.x * blockDim.x + threadIdx.x;
    if (i < n) p[i] = 0;
}

__global__ void hist_kernel(const int* __restrict__ dst, int* __restrict__ deg, int E) {
    int i = blockIdx.x * blockDim.x + threadIdx.x;
    if (i < E) atomicAdd(&deg[dst[i]], 1);
}

// Single-block exclusive scan over n <= 131072 elements (1024 thr x chunk).
__global__ __launch_bounds__(1024)
void scan_kernel(const int* __restrict__ deg, int* __restrict__ off, int n) {
    __shared__ int partial[1024];
    int tid = threadIdx.x;
    int chunk = (n + 1023) >> 10;
    int base = tid * chunk;
    int s = 0;
    for (int i = 0; i < chunk; ++i) {
        int idx = base + i;
        if (idx < n) s += deg[idx];
    }
    partial[tid] = s;
    __syncthreads();
    for (int d = 1; d < 1024; d <<= 1) {
        int v = (tid >= d) ? partial[tid - d] : 0;
        __syncthreads();
        partial[tid] += v;
        __syncthreads();
    }
    int run = (tid == 0) ? 0 : partial[tid - 1];
    for (int i = 0; i < chunk; ++i) {
        int idx = base + i;
        if (idx < n) { off[idx] = run; run += deg[idx]; }
    }
    if (tid == 1023) off[n] = partial[1023];
}

__global__ void copy_int_kernel(const int* __restrict__ a, int* __restrict__ b, int n) {
    int i = blockIdx.x * blockDim.x + threadIdx.x;
    if (i < n) b[i] = a[i];
}

__global__ void fill_kernel(const int* __restrict__ src, const int* __restrict__ dst,
                            int* __restrict__ pos, int* __restrict__ csr, int E) {
    int i = blockIdx.x * blockDim.x + threadIdx.x;
    if (i < E) {
        int slot = atomicAdd(&pos[dst[i]], 1);
        csr[slot] = src[i];
    }
}

// ---------------------------------------------------------------------------
// CSR aggregation: one warp per dst row. Accumulate all neighbor rows in
// registers (8 f32/lane), single streaming store. No RMW traffic at all.
// ---------------------------------------------------------------------------
__global__ void csr_aggregate_kernel(const float* __restrict__ X,
                                     const int* __restrict__ csr,
                                     const int* __restrict__ off,
                                     float* __restrict__ agg, int nrows) {
    int row = blockIdx.x * (blockDim.x >> 5) + (threadIdx.x >> 5);
    if (row >= nrows) return;
    int lane = threadIdx.x & 31;
    int beg = off[row], end = off[row + 1];

    float4 a0 = make_float4(0.f, 0.f, 0.f, 0.f);
    float4 a1 = make_float4(0.f, 0.f, 0.f, 0.f);

    int e = beg;
    for (; e + 4 <= end; e += 4) {
        int s0 = __ldg(&csr[e + 0]);
        int s1 = __ldg(&csr[e + 1]);
        int s2 = __ldg(&csr[e + 2]);
        int s3 = __ldg(&csr[e + 3]);
        const float4* p0 = (const float4*)(X + (size_t)s0 * DIM);
        const float4* p1 = (const float4*)(X + (size_t)s1 * DIM);
        const float4* p2 = (const float4*)(X + (size_t)s2 * DIM);
        const float4* p3 = (const float4*)(X + (size_t)s3 * DIM);
        float4 u0 = __ldg(p0 + lane), w0 = __ldg(p0 + lane + 32);
        float4 u1 = __ldg(p1 + lane), w1 = __ldg(p1 + lane + 32);
        float4 u2 = __ldg(p2 + lane), w2 = __ldg(p2 + lane + 32);
        float4 u3 = __ldg(p3 + lane), w3 = __ldg(p3 + lane + 32);
        a0.x += u0.x + u1.x + u2.x + u3.x;
        a0.y += u0.y + u1.y + u2.y + u3.y;
        a0.z += u0.z + u1.z + u2.z + u3.z;
        a0.w += u0.w + u1.w + u2.w + u3.w;
        a1.x += w0.x + w1.x + w2.x + w3.x;
        a1.y += w0.y + w1.y + w2.y + w3.y;
        a1.z += w0.z + w1.z + w2.z + w3.z;
        a1.w += w0.w + w1.w + w2.w + w3.w;
    }
    for (; e < end; ++e) {
        int s = __ldg(&csr[e]);
        const float4* p = (const float4*)(X + (size_t)s * DIM);
        float4 u = __ldg(p + lane), w = __ldg(p + lane + 32);
        a0.x += u.x; a0.y += u.y; a0.z += u.z; a0.w += u.w;
        a1.x += w.x; a1.y += w.y; a1.z += w.z; a1.w += w.w;
    }
    float4* ap = (float4*)(agg + (size_t)row * DIM);
    ap[lane]      = a0;
    ap[lane + 32] = a1;
}

// ---------------------------------------------------------------------------
// TF32 tensor-core fused dual-A GEMM, double-buffered, 64x64 warp tiles.
//   C = relu?( A1 @ B1 + A2 @ B2 + bias )
// 128 threads = 4 warps (2M x 2N), block tile 128x128, BK=16, virtual K=512.
// A staged in FRAGMENT-MAJOR smem layout: each thread's 4 A-frag regs are one
// contiguous float4 (XOR row swizzle keeps frag loads conflict-free).
// cvt.rna.tf32 applied at smem-store time (accuracy requirement).
// ---------------------------------------------------------------------------
#define BM 128
#define BN 128
#define BK 16
#define BPAD 8

__device__ __forceinline__ float f2tf32(float x) {
    uint32_t r;
    asm("cvt.rna.tf32.f32 %0, %1;" : "=r"(r) : "f"(x));
    return __uint_as_float(r);
}

__device__ __forceinline__ void mma_tf32(float c[4], const uint32_t a[4], const uint32_t b[2]) {
    asm volatile(
        "mma.sync.aligned.m16n8k8.row.col.f32.tf32.tf32.f32 "
        "{%0,%1,%2,%3}, {%4,%5,%6,%7}, {%8,%9}, {%0,%1,%2,%3};"
        : "+f"(c[0]), "+f"(c[1]), "+f"(c[2]), "+f"(c[3])
        : "r"(a[0]), "r"(a[1]), "r"(a[2]), "r"(a[3]), "r"(b[0]), "r"(b[1]));
}

// Fragment-major A address (in floats) for element (m, k) of the 128x16 tile.
// L = linear "lane slot": frag float4 for (kk2, wr, i) at lane -> L = ((kk2*2+wr)*4+i)*32 + lane
// reg r = mh + 2*kh  (mh = (m>>3)&1, kh = (k>>2)&1). XOR swizzle on L's low 3 bits by row.
__device__ __forceinline__ int a_frag_addr(int m, int k) {
    int wrp = m >> 6;
    int it  = (m >> 4) & 3;
    int mh  = (m >> 3) & 1;
    int gd  = m & 7;
    int kk2 = k >> 3;
    int kh  = (k >> 2) & 1;
    int tg  = k & 3;
    int L   = ((kk2 * 2 + wrp) * 4 + it) * 32 + (gd << 2) + tg;
    int srow = L >> 3;
    int scol = (L & 7) ^ (srow & 7);
    return srow * 32 + scol * 4 + (mh + 2 * kh);
}

__global__ __launch_bounds__(128, 2)
void sage_gemm_tc_kernel(const float* __restrict__ A1, const float* __restrict__ A2,
                         const float* __restrict__ B1, const float* __restrict__ B2,
                         const float* __restrict__ bias, float* __restrict__ C,
                         int M, int relu) {
    __shared__ float Asw[2][BM * BK];            // fragment-major, swizzled
    __shared__ float Bs[2][BK][BN + BPAD];

    const int tid  = threadIdx.x;
    const int lane = tid & 31;
    const int wid  = tid >> 5;
    const int tg   = lane & 3;
    const int gid  = lane >> 2;
    const int wr   = wid >> 1;          // 0..1 -> M
    const int wn   = (wid & 1) * 64;    // 0..1 -> N
    const int wm   = wr * 64;
    const int m0   = blockIdx.x * BM;
    const int n0   = blockIdx.y * BN;
    const int K = DIM, N = DIM;
    const int T = 2 * (DIM / BK);       // 32 tiles

    // staging indices: A 512 float4 / 128 thr = 4 (rows r0+32p, kc4 fixed)
    const int arow = tid >> 2;          // 0..31
    const int akc4 = tid & 3;           // float4 col within BK
    // B 512 float4 / 128 thr = 4 (krow kr0+4p, nc4 fixed)
    const int bkr  = tid >> 5;          // 0..3
    const int bnc4 = tid & 31;

    float acc[4][8][4];
#pragma unroll
    for (int i = 0; i < 4; ++i)
#pragma unroll
        for (int j = 0; j < 8; ++j)
#pragma unroll
            for (int r = 0; r < 4; ++r) acc[i][j][r] = 0.f;

    float4 pa[4], pb[4];

    auto load_tile = [&](int t) {
        const float* __restrict__ A = (t < T / 2) ? A1 : A2;
        const float* __restrict__ B = (t < T / 2) ? B1 : B2;
        int kt = (t & (T / 2 - 1)) * BK;
#pragma unroll
        for (int p = 0; p < 4; ++p) {
            int row = arow + p * 32;
            int gr = m0 + row;
            pa[p] = (gr < M) ? *(const float4*)&A[(size_t)gr * K + kt + akc4 * 4]
                             : make_float4(0.f, 0.f, 0.f, 0.f);
        }
#pragma unroll
        for (int p = 0; p < 4; ++p) {
            int krow = bkr + p * 4;
            pb[p] = *(const float4*)&B[(size_t)(kt + krow) * N + n0 + bnc4 * 4];
        }
    };

    auto store_tile = [&](int s) {
#pragma unroll
        for (int p = 0; p < 4; ++p) {
            int row = arow + p * 32;
            float v[4] = {pa[p].x, pa[p].y, pa[p].z, pa[p].w};
#pragma unroll
            for (int e = 0; e < 4; ++e)
                Asw[s][a_frag_addr(row, akc4 * 4 + e)] = f2tf32(v[e]);
        }
#pragma unroll
        for (int p = 0; p < 4; ++p) {
            int krow = bkr + p * 4;
            float4 t;
            t.x = f2tf32(pb[p].x); t.y = f2tf32(pb[p].y);
            t.z = f2tf32(pb[p].z); t.w = f2tf32(pb[p].w);
            *(float4*)&Bs[s][krow][bnc4 * 4] = t;
        }
    };

    // prologue
    load_tile(0);
    store_tile(0);
    __syncthreads();

#pragma unroll 1
    for (int t = 0; t < T; ++t) {
        if (t + 1 < T) load_tile(t + 1);
        const int st = t & 1;
#pragma unroll
        for (int kk2 = 0; kk2 < 2; ++kk2) {
            uint32_t af[4][4], bf[8][2];
#pragma unroll
            for (int i = 0; i < 4; ++i) {
                int L = ((kk2 * 2 + wr) * 4 + i) * 32 + lane;
                int srow = L >> 3;
                int scol = (L & 7) ^ (srow & 7);
                float4 v = *(const float4*)&Asw[st][srow * 32 + scol * 4];
                af[i][0] = __float_as_uint(v.x);
                af[i][1] = __float_as_uint(v.y);
                af[i][2] = __float_as_uint(v.z);
                af[i][3] = __float_as_uint(v.w);
            }
#pragma unroll
            for (int j = 0; j < 8; ++j) {
                int nc = wn + j * 8 + gid;
                bf[j][0] = __float_as_uint(Bs[st][kk2 * 8 + tg][nc]);
                bf[j][1] = __float_as_uint(Bs[st][kk2 * 8 + tg + 4][nc]);
            }
#pragma unroll
            for (int i = 0; i < 4; ++i)
#pragma unroll
                for (int j = 0; j < 8; ++j)
                    mma_tf32(acc[i][j], af[i], bf[j]);
        }
        if (t + 1 < T) {
            store_tile((t + 1) & 1);
            __syncthreads();
        }
    }

    // epilogue: bias (+relu), float2 stores
#pragma unroll
    for (int i = 0; i < 4; ++i) {
#pragma unroll
        for (int rh = 0; rh < 2; ++rh) {
            int row = m0 + wm + i * 16 + gid + rh * 8;
            if (row >= M) continue;
#pragma unroll
            for (int j = 0; j < 8; ++j) {
                int col = n0 + wn + j * 8 + tg * 2;
                float2 v;
                v.x = acc[i][j][rh * 2 + 0] + bias[col + 0];
                v.y = acc[i][j][rh * 2 + 1] + bias[col + 1];
                if (relu) { v.x = fmaxf(v.x, 0.f); v.y = fmaxf(v.y, 0.f); }
                *(float2*)&C[(size_t)row * N + col] = v;
            }
        }
    }
}

// ---------------------------------------------------------------------------
// Final layer: out[M, 47] = h @ Wself + agg @ Wneigh + bias  (no relu)
// ---------------------------------------------------------------------------
__global__ __launch_bounds__(64)
void sage_out_kernel(const float* __restrict__ h, const float* __restrict__ agg,
                     const float* __restrict__ Ws, const float* __restrict__ Wn,
                     const float* __restrict__ bias, float* __restrict__ out) {
    int row = blockIdx.x;
    __shared__ float sh[DIM];
    __shared__ float sa[DIM];
    for (int i = threadIdx.x; i < DIM; i += 64) {
        sh[i] = h[(size_t)row * DIM + i];
        sa[i] = agg[(size_t)row * DIM + i];
    }
    __syncthreads();
    int j = threadIdx.x;
    if (j < COUT) {
        float acc = bias[j];
#pragma unroll 4
        for (int k = 0; k < DIM; ++k) {
            acc = fmaf(sh[k], Ws[k * COUT + j], acc);
            acc = fmaf(sa[k], Wn[k * COUT + j], acc);
        }
        out[(size_t)row * COUT + j] = acc;
    }
}

// ---------------------------------------------------------------------------
// Host-side helper: build CSR + aggregate for one layer
// ---------------------------------------------------------------------------
static void build_and_aggregate(const float* X, const int* src, const int* dst,
                                float* agg, int E, int nrows,
                                int* deg, int* off, int* pos, int* csr) {
    zero_int_kernel<<<(nrows + 255) / 256, 256>>>(deg, nrows);
    hist_kernel<<<(E + 255) / 256, 256>>>(dst, deg, E);
    scan_kernel<<<1, 1024>>>(deg, off, nrows);
    copy_int_kernel<<<(nrows + 255) / 256, 256>>>(off, pos, nrows);
    fill_kernel<<<(E + 255) / 256, 256>>>(src, dst, pos, csr, E);
    csr_aggregate_kernel<<<(nrows + 7) / 8, 256>>>(X, csr, off, agg, nrows);
}

// ---------------------------------------------------------------------------
// Launch
// ---------------------------------------------------------------------------
extern "C" void kernel_launch(void* const* d_in, const int* in_sizes, int n_in,
                              void* d_out, int out_size) {
    const float* x   = (const float*)d_in[0];
    const int* src0  = (const int*)d_in[1];
    const int* dst0  = (const int*)d_in[2];
    const int* src1  = (const int*)d_in[3];
    const int* dst1  = (const int*)d_in[4];
    const int* src2  = (const int*)d_in[5];
    const int* dst2  = (const int*)d_in[6];
    const float* ws0 = (const float*)d_in[7];
    const float* wn0 = (const float*)d_in[8];
    const float* b0  = (const float*)d_in[9];
    const float* ws1 = (const float*)d_in[10];
    const float* wn1 = (const float*)d_in[11];
    const float* b1  = (const float*)d_in[12];
    const float* ws2 = (const float*)d_in[13];
    const float* wn2 = (const float*)d_in[14];
    const float* b2  = (const float*)d_in[15];

    const int E0 = in_sizes[1];
    const int E1 = in_sizes[3];
    const int E2 = in_sizes[5];

    float *agg0, *h1, *agg1, *h2, *agg2;
    int *deg, *off, *pos, *csr;
    cudaGetSymbolAddress((void**)&agg0, g_agg0);
    cudaGetSymbolAddress((void**)&h1,   g_h1);
    cudaGetSymbolAddress((void**)&agg1, g_agg1);
    cudaGetSymbolAddress((void**)&h2,   g_h2);
    cudaGetSymbolAddress((void**)&agg2, g_agg2);
    cudaGetSymbolAddress((void**)&deg,  g_deg);
    cudaGetSymbolAddress((void**)&off,  g_off);
    cudaGetSymbolAddress((void**)&pos,  g_pos);
    cudaGetSymbolAddress((void**)&csr,  g_csr);

    float* out = (float*)d_out;

    // Layer 0
    build_and_aggregate(x, src0, dst0, agg0, E0, N1, deg, off, pos, csr);
    {
        dim3 grid((N1 + BM - 1) / BM, DIM / BN);
        sage_gemm_tc_kernel<<<grid, 128>>>(x, agg0, ws0, wn0, b0, h1, N1, 1);
    }

    // Layer 1
    build_and_aggregate(h1, src1, dst1, agg1, E1, N2, deg, off, pos, csr);
    {
        dim3 grid((N2 + BM - 1) / BM, DIM / BN);
        sage_gemm_tc_kernel<<<grid, 128>>>(h1, agg1, ws1, wn1, b1, h2, N2, 1);
    }

    // Layer 2 (output, N=47, no relu)
    build_and_aggregate(h2, src2, dst2, agg2, E2, N3, deg, off, pos, csr);
    sage_out_kernel<<<N3, 64>>>(h2, agg2, ws2, wn2, b2, out);
}